// round 1
// baseline (speedup 1.0000x reference)
#include <cuda_runtime.h>
#include <math.h>

#define Bb 8
#define Nn 4096
#define Dd 128
#define Hh 8
#define DHh 16
#define FFf 512
#define Kk 16
#define Ll 2

// ---------------- scratch (static device globals; no allocations) ----------
__device__ float g_feat[Bb * Nn * Dd];       // 16 MB
__device__ float g_h[Bb * Nn * Dd];          // 16 MB
__device__ float g_qkv[Bb * Nn * 3 * Dd];    // 48 MB (also reused as proj/f2 tmp)
__device__ float g_attn[Bb * Nn * Dd];       // 16 MB
__device__ float g_ff[Bb * Nn * FFf];        // 64 MB
__device__ int   g_knn[Bb * Nn * Kk];
__device__ float g_pooled[Bb * Dd];

// ---------------- embed: feat = xyz@W1^T + b1 + ohe@W2^T + b2 --------------
__global__ void embed_kernel(const float* __restrict__ x,
                             const float* __restrict__ xyz_w, const float* __restrict__ xyz_b,
                             const float* __restrict__ ohe_w, const float* __restrict__ ohe_b) {
    int i = blockIdx.x * blockDim.x + threadIdx.x;
    if (i >= Bb * Nn * Dd) return;
    int d = i & (Dd - 1);
    int bn = i >> 7;
    const float* xr = x + (size_t)bn * 8;
    float acc = xyz_b[d] + ohe_b[d];
#pragma unroll
    for (int j = 0; j < 3; j++) acc += xr[j] * xyz_w[d * 3 + j];
#pragma unroll
    for (int j = 0; j < 5; j++) acc += xr[3 + j] * ohe_w[d * 5 + j];
    g_feat[i] = acc;
}

// ---------------- exact KNN: top K+1 smallest d2, drop self ----------------
__global__ void knn_select_kernel(const float* __restrict__ x) {
    int b = blockIdx.y, n = blockIdx.x;
    __shared__ float d2s[Nn];
    __shared__ float bv[128];
    __shared__ int bi[128];
    const float* xb = x + (size_t)b * Nn * 8;
    float qx = xb[n * 8 + 0], qy = xb[n * 8 + 1], qz = xb[n * 8 + 2];
    for (int j = threadIdx.x; j < Nn; j += 128) {
        float dx = xb[j * 8 + 0] - qx;
        float dy = xb[j * 8 + 1] - qy;
        float dz = xb[j * 8 + 2] - qz;
        d2s[j] = dx * dx + dy * dy + dz * dz;
    }
    __syncthreads();
    for (int it = 0; it <= Kk; ++it) {
        float mv = 3.4e38f;
        int mi = 0x7fffffff;
        for (int j = threadIdx.x; j < Nn; j += 128) {
            float v = d2s[j];
            if (v < mv) { mv = v; mi = j; }  // strict < keeps lowest index per thread
        }
        bv[threadIdx.x] = mv;
        bi[threadIdx.x] = mi;
        __syncthreads();
        for (int s = 64; s > 0; s >>= 1) {
            if (threadIdx.x < s) {
                float v2 = bv[threadIdx.x + s];
                int i2 = bi[threadIdx.x + s];
                if (v2 < bv[threadIdx.x] ||
                    (v2 == bv[threadIdx.x] && i2 < bi[threadIdx.x])) {
                    bv[threadIdx.x] = v2;
                    bi[threadIdx.x] = i2;
                }
            }
            __syncthreads();
        }
        if (threadIdx.x == 0) {
            int sel = bi[0];
            d2s[sel] = 3.4e38f;
            if (it > 0) g_knn[((size_t)b * Nn + n) * Kk + (it - 1)] = sel;
        }
        __syncthreads();
    }
}

// ---------------- KNN attention: one warp per (b,n) ------------------------
__global__ void knn_attn_kernel() {
    int gw = (blockIdx.x * blockDim.x + threadIdx.x) >> 5;
    int lane = threadIdx.x & 31;
    if (gw >= Bb * Nn) return;
    int b = gw >> 12;
    int n = gw & (Nn - 1);
    const float* fb = g_feat + (size_t)b * Nn * Dd;
    const float* qr = fb + (size_t)n * Dd;
    float q0 = qr[lane], q1 = qr[lane + 32], q2 = qr[lane + 64], q3 = qr[lane + 96];
    const int* idxp = g_knn + (size_t)gw * Kk;
    int idx[Kk];
#pragma unroll
    for (int k = 0; k < Kk; k++) idx[k] = idxp[k];
    float sc[Kk];
    const float scale = 0.08838834764831845f;  // 1/sqrt(128)
#pragma unroll
    for (int k = 0; k < Kk; k++) {
        const float* fr = fb + (size_t)idx[k] * Dd;
        float p = q0 * fr[lane] + q1 * fr[lane + 32] + q2 * fr[lane + 64] + q3 * fr[lane + 96];
#pragma unroll
        for (int o = 16; o > 0; o >>= 1) p += __shfl_xor_sync(0xffffffffu, p, o);
        sc[k] = p * scale;
    }
    float m = sc[0];
#pragma unroll
    for (int k = 1; k < Kk; k++) m = fmaxf(m, sc[k]);
    float l = 0.f;
#pragma unroll
    for (int k = 0; k < Kk; k++) { sc[k] = expf(sc[k] - m); l += sc[k]; }
    float inv = 1.f / l;
    float o0 = 0.f, o1 = 0.f, o2 = 0.f, o3 = 0.f;
#pragma unroll
    for (int k = 0; k < Kk; k++) {
        float w = sc[k] * inv;
        const float* fr = fb + (size_t)idx[k] * Dd;
        o0 += w * fr[lane];
        o1 += w * fr[lane + 32];
        o2 += w * fr[lane + 64];
        o3 += w * fr[lane + 96];
    }
    float* hr = g_h + (size_t)(b * Nn + n) * Dd;
    hr[lane] = o0; hr[lane + 32] = o1; hr[lane + 64] = o2; hr[lane + 96] = o3;
}

// ---------------- tiled fp32 GEMM: C = A(MxK) * W(NxK)^T + bias ------------
__global__ void gemm_bias_kernel(const float* __restrict__ A, const float* __restrict__ W,
                                 const float* __restrict__ bias, float* __restrict__ C,
                                 int M, int Nd, int Kd, int relu) {
    const int BM = 64, BN = 64, BK = 16;
    __shared__ float As[BK][BM];
    __shared__ float Ws[BK][BN];
    int n0 = blockIdx.x * BN;
    int m0 = blockIdx.y * BM;
    int tid = threadIdx.x;
    int tx = tid & 15, ty = tid >> 4;
    int lr = tid >> 2;          // row 0..63
    int lc = (tid & 3) * 4;     // k 0,4,8,12
    float acc[4][4] = {};
    for (int k0 = 0; k0 < Kd; k0 += BK) {
        float4 av = *(const float4*)(A + (size_t)(m0 + lr) * Kd + k0 + lc);
        float4 wv = *(const float4*)(W + (size_t)(n0 + lr) * Kd + k0 + lc);
        As[lc + 0][lr] = av.x; As[lc + 1][lr] = av.y; As[lc + 2][lr] = av.z; As[lc + 3][lr] = av.w;
        Ws[lc + 0][lr] = wv.x; Ws[lc + 1][lr] = wv.y; Ws[lc + 2][lr] = wv.z; Ws[lc + 3][lr] = wv.w;
        __syncthreads();
#pragma unroll
        for (int k = 0; k < BK; k++) {
            float a[4], w[4];
#pragma unroll
            for (int i = 0; i < 4; i++) a[i] = As[k][ty * 4 + i];
#pragma unroll
            for (int j = 0; j < 4; j++) w[j] = Ws[k][tx * 4 + j];
#pragma unroll
            for (int i = 0; i < 4; i++)
#pragma unroll
                for (int j = 0; j < 4; j++) acc[i][j] += a[i] * w[j];
        }
        __syncthreads();
    }
#pragma unroll
    for (int i = 0; i < 4; i++) {
#pragma unroll
        for (int j = 0; j < 4; j++) {
            float v = acc[i][j] + bias[n0 + tx * 4 + j];
            if (relu) v = fmaxf(v, 0.f);
            C[(size_t)(m0 + ty * 4 + i) * Nd + n0 + tx * 4 + j] = v;
        }
    }
}

// ---------------- MHA (streaming softmax, 1 query/thread) ------------------
__global__ void mha_kernel() {
    int b = blockIdx.z, h = blockIdx.y;
    int n = blockIdx.x * 128 + threadIdx.x;
    const float* qkvb = g_qkv + (size_t)b * Nn * (3 * Dd);
    float q[DHh];
#pragma unroll
    for (int d = 0; d < DHh; d++) q[d] = qkvb[(size_t)n * 384 + h * 16 + d] * 0.25f;
    __shared__ float ks[64][16];
    __shared__ float vs[64][16];
    float m = -1e30f, l = 0.f;
    float acc[DHh] = {};
    int row = threadIdx.x >> 1;
    int half = (threadIdx.x & 1) * 8;
    for (int kt = 0; kt < Nn; kt += 64) {
        const float* kr = qkvb + (size_t)(kt + row) * 384 + 128 + h * 16 + half;
        const float* vr = qkvb + (size_t)(kt + row) * 384 + 256 + h * 16 + half;
        *(float4*)&ks[row][half] = *(const float4*)kr;
        *(float4*)&ks[row][half + 4] = *(const float4*)(kr + 4);
        *(float4*)&vs[row][half] = *(const float4*)vr;
        *(float4*)&vs[row][half + 4] = *(const float4*)(vr + 4);
        __syncthreads();
#pragma unroll 2
        for (int j = 0; j < 64; j++) {
            float s = 0.f;
#pragma unroll
            for (int d = 0; d < DHh; d++) s += q[d] * ks[j][d];
            if (s > m) {
                float c = expf(m - s);
                l *= c;
#pragma unroll
                for (int d = 0; d < DHh; d++) acc[d] *= c;
                m = s;
            }
            float p = expf(s - m);
            l += p;
#pragma unroll
            for (int d = 0; d < DHh; d++) acc[d] += p * vs[j][d];
        }
        __syncthreads();
    }
    float inv = 1.f / l;
    float* op = g_attn + (size_t)(b * Nn + n) * Dd + h * 16;
#pragma unroll
    for (int d = 0; d < DHh; d++) op[d] = acc[d] * inv;
}

// ---------------- fused residual-add + LayerNorm (warp per row) ------------
__global__ void add_ln_kernel(float* __restrict__ h, const float* __restrict__ r,
                              const float* __restrict__ w, const float* __restrict__ bg) {
    int row = blockIdx.x * 8 + (threadIdx.x >> 5);
    int lane = threadIdx.x & 31;
    float* hp = h + (size_t)row * Dd;
    const float* rp = r + (size_t)row * Dd;
    float v[4];
    float s = 0.f;
#pragma unroll
    for (int i = 0; i < 4; i++) {
        v[i] = hp[lane + 32 * i] + rp[lane + 32 * i];
        s += v[i];
    }
#pragma unroll
    for (int o = 16; o > 0; o >>= 1) s += __shfl_xor_sync(0xffffffffu, s, o);
    float mean = s * (1.f / Dd);
    float var = 0.f;
#pragma unroll
    for (int i = 0; i < 4; i++) {
        float t = v[i] - mean;
        var += t * t;
    }
#pragma unroll
    for (int o = 16; o > 0; o >>= 1) var += __shfl_xor_sync(0xffffffffu, var, o);
    float inv = rsqrtf(var * (1.f / Dd) + 1e-5f);
#pragma unroll
    for (int i = 0; i < 4; i++)
        hp[lane + 32 * i] = (v[i] - mean) * inv * w[lane + 32 * i] + bg[lane + 32 * i];
}

// ---------------- mean pool over N ----------------------------------------
__global__ void pool_kernel() {
    int b = blockIdx.x;
    int d = threadIdx.x;
    float s = 0.f;
    for (int n = 0; n < Nn; n++) s += g_h[((size_t)b * Nn + n) * Dd + d];
    g_pooled[b * Dd + d] = s * (1.f / Nn);
}

// ---------------- final MLP head -------------------------------------------
__global__ void head_kernel(const float* __restrict__ fc1w, const float* __restrict__ fc1b,
                            const float* __restrict__ fc2w, const float* __restrict__ fc2b,
                            float* __restrict__ out) {
    int b = blockIdx.x;
    __shared__ float ps[128];
    float partial = 0.f;
    for (int f = threadIdx.x; f < FFf; f += 128) {
        float s = fc1b[f];
#pragma unroll 4
        for (int d = 0; d < Dd; d++) s += g_pooled[b * Dd + d] * fc1w[f * Dd + d];
        s = fmaxf(s, 0.f);
        partial += s * fc2w[f];
    }
    ps[threadIdx.x] = partial;
    __syncthreads();
    for (int s = 64; s > 0; s >>= 1) {
        if (threadIdx.x < s) ps[threadIdx.x] += ps[threadIdx.x + s];
        __syncthreads();
    }
    if (threadIdx.x == 0) {
        float z = ps[0] + fc2b[0];
        out[b] = 1.f / (1.f + expf(-z));
    }
}

// ---------------- host launcher --------------------------------------------
extern "C" void kernel_launch(void* const* d_in, const int* in_sizes, int n_in,
                              void* d_out, int out_size) {
    const float* x       = (const float*)d_in[0];
    const float* xyz_w   = (const float*)d_in[1];
    const float* xyz_b   = (const float*)d_in[2];
    const float* ohe_w   = (const float*)d_in[3];
    const float* ohe_b   = (const float*)d_in[4];
    const float* in_w    = (const float*)d_in[5];
    const float* in_b    = (const float*)d_in[6];
    const float* out_w   = (const float*)d_in[7];
    const float* out_b   = (const float*)d_in[8];
    const float* ln1_w   = (const float*)d_in[9];
    const float* ln1_b   = (const float*)d_in[10];
    const float* lin1_w  = (const float*)d_in[11];
    const float* lin1_b  = (const float*)d_in[12];
    const float* lin2_w  = (const float*)d_in[13];
    const float* lin2_b  = (const float*)d_in[14];
    const float* ln2_w   = (const float*)d_in[15];
    const float* ln2_b   = (const float*)d_in[16];
    const float* fc1_w   = (const float*)d_in[17];
    const float* fc1_b   = (const float*)d_in[18];
    const float* fc2_w   = (const float*)d_in[19];
    const float* fc2_b   = (const float*)d_in[20];
    float* out = (float*)d_out;

    float *p_h, *p_qkv, *p_attn, *p_ff;
    cudaGetSymbolAddress((void**)&p_h, g_h);
    cudaGetSymbolAddress((void**)&p_qkv, g_qkv);
    cudaGetSymbolAddress((void**)&p_attn, g_attn);
    cudaGetSymbolAddress((void**)&p_ff, g_ff);

    const int M = Bb * Nn;  // 32768

    // 1. embed
    embed_kernel<<<(Bb * Nn * Dd + 255) / 256, 256>>>(x, xyz_w, xyz_b, ohe_w, ohe_b);
    // 2. knn select
    knn_select_kernel<<<dim3(Nn, Bb), 128>>>(x);
    // 3. knn attention -> h
    knn_attn_kernel<<<(Bb * Nn * 32 + 127) / 128, 128>>>();

    for (int l = 0; l < Ll; l++) {
        // qkv = h @ in_w^T + in_b
        gemm_bias_kernel<<<dim3(384 / 64, M / 64), 256>>>(
            p_h, in_w + (size_t)l * 384 * 128, in_b + (size_t)l * 384, p_qkv, M, 384, 128, 0);
        // attention
        mha_kernel<<<dim3(Nn / 128, Hh, Bb), 128>>>();
        // out proj (write to qkv region as tmp)
        gemm_bias_kernel<<<dim3(128 / 64, M / 64), 256>>>(
            p_attn, out_w + (size_t)l * 128 * 128, out_b + (size_t)l * 128, p_qkv, M, 128, 128, 0);
        // h = LN(h + proj)
        add_ln_kernel<<<M / 8, 256>>>(p_h, p_qkv, ln1_w + l * 128, ln1_b + l * 128);
        // ff1 = relu(h @ lin1^T + b)
        gemm_bias_kernel<<<dim3(512 / 64, M / 64), 256>>>(
            p_h, lin1_w + (size_t)l * 512 * 128, lin1_b + (size_t)l * 512, p_ff, M, 512, 128, 1);
        // f2 = ff1 @ lin2^T + b   (qkv region as tmp)
        gemm_bias_kernel<<<dim3(128 / 64, M / 64), 256>>>(
            p_ff, lin2_w + (size_t)l * 128 * 512, lin2_b + (size_t)l * 128, p_qkv, M, 128, 512, 0);
        // h = LN(h + f2)
        add_ln_kernel<<<M / 8, 256>>>(p_h, p_qkv, ln2_w + l * 128, ln2_b + l * 128);
    }

    // pool + head
    pool_kernel<<<Bb, Dd>>>();
    head_kernel<<<Bb, 128>>>(fc1_w, fc1_b, fc2_w, fc2_b, out);
}

// round 3
// speedup vs baseline: 1.9939x; 1.9939x over previous
#include <cuda_runtime.h>
#include <cuda_bf16.h>
#include <math.h>
#include <stdint.h>

#define Bb 8
#define Nn 4096
#define Dd 128
#define Hh 8
#define DHh 16
#define FFf 512
#define Kk 16
#define Ll 2

// ---------------- scratch (static device globals; no allocations) ----------
__device__ float g_feat[Bb * Nn * Dd];       // 16 MB
__device__ float g_h[Bb * Nn * Dd];          // 16 MB
__device__ float g_qkv[Bb * Nn * 3 * Dd];    // 48 MB (also reused as proj/f2 tmp)
__device__ float g_attn[Bb * Nn * Dd];       // 16 MB
__device__ float g_ff[Bb * Nn * FFf];        // 64 MB
__device__ int   g_knn[Bb * Nn * Kk];
__device__ float g_pooled[Bb * Dd];
// bf16 attention operands (head-major)
__device__ __nv_bfloat16 g_qbf[Bb * Hh * Nn * DHh];   // 8 MB
__device__ __nv_bfloat16 g_kbf[Bb * Hh * Nn * DHh];   // 8 MB
__device__ __nv_bfloat16 g_vtbf[Bb * Hh * DHh * Nn];  // 8 MB (V transposed: [bh][d][n])

// ---------------- embed: feat = xyz@W1^T + b1 + ohe@W2^T + b2 --------------
__global__ void embed_kernel(const float* __restrict__ x,
                             const float* __restrict__ xyz_w, const float* __restrict__ xyz_b,
                             const float* __restrict__ ohe_w, const float* __restrict__ ohe_b) {
    int i = blockIdx.x * blockDim.x + threadIdx.x;
    if (i >= Bb * Nn * Dd) return;
    int d = i & (Dd - 1);
    int bn = i >> 7;
    const float* xr = x + (size_t)bn * 8;
    float acc = xyz_b[d] + ohe_b[d];
#pragma unroll
    for (int j = 0; j < 3; j++) acc += xr[j] * xyz_w[d * 3 + j];
#pragma unroll
    for (int j = 0; j < 5; j++) acc += xr[3 + j] * ohe_w[d * 5 + j];
    g_feat[i] = acc;
}

// ---------------- exact KNN: top K+1 smallest d2, drop self ----------------
__global__ void knn_select_kernel(const float* __restrict__ x) {
    int b = blockIdx.y, n = blockIdx.x;
    __shared__ float d2s[Nn];
    __shared__ float bv[128];
    __shared__ int bi[128];
    const float* xb = x + (size_t)b * Nn * 8;
    float qx = xb[n * 8 + 0], qy = xb[n * 8 + 1], qz = xb[n * 8 + 2];
    for (int j = threadIdx.x; j < Nn; j += 128) {
        float dx = xb[j * 8 + 0] - qx;
        float dy = xb[j * 8 + 1] - qy;
        float dz = xb[j * 8 + 2] - qz;
        d2s[j] = dx * dx + dy * dy + dz * dz;
    }
    __syncthreads();
    for (int it = 0; it <= Kk; ++it) {
        float mv = 3.4e38f;
        int mi = 0x7fffffff;
        for (int j = threadIdx.x; j < Nn; j += 128) {
            float v = d2s[j];
            if (v < mv) { mv = v; mi = j; }
        }
        bv[threadIdx.x] = mv;
        bi[threadIdx.x] = mi;
        __syncthreads();
        for (int s = 64; s > 0; s >>= 1) {
            if (threadIdx.x < s) {
                float v2 = bv[threadIdx.x + s];
                int i2 = bi[threadIdx.x + s];
                if (v2 < bv[threadIdx.x] ||
                    (v2 == bv[threadIdx.x] && i2 < bi[threadIdx.x])) {
                    bv[threadIdx.x] = v2;
                    bi[threadIdx.x] = i2;
                }
            }
            __syncthreads();
        }
        if (threadIdx.x == 0) {
            int sel = bi[0];
            d2s[sel] = 3.4e38f;
            if (it > 0) g_knn[((size_t)b * Nn + n) * Kk + (it - 1)] = sel;
        }
        __syncthreads();
    }
}

// ---------------- KNN attention: one warp per (b,n) ------------------------
__global__ void knn_attn_kernel() {
    int gw = (blockIdx.x * blockDim.x + threadIdx.x) >> 5;
    int lane = threadIdx.x & 31;
    if (gw >= Bb * Nn) return;
    int b = gw >> 12;
    int n = gw & (Nn - 1);
    const float* fb = g_feat + (size_t)b * Nn * Dd;
    const float* qr = fb + (size_t)n * Dd;
    float q0 = qr[lane], q1 = qr[lane + 32], q2 = qr[lane + 64], q3 = qr[lane + 96];
    const int* idxp = g_knn + (size_t)gw * Kk;
    int idx[Kk];
#pragma unroll
    for (int k = 0; k < Kk; k++) idx[k] = idxp[k];
    float sc[Kk];
    const float scale = 0.08838834764831845f;
#pragma unroll
    for (int k = 0; k < Kk; k++) {
        const float* fr = fb + (size_t)idx[k] * Dd;
        float p = q0 * fr[lane] + q1 * fr[lane + 32] + q2 * fr[lane + 64] + q3 * fr[lane + 96];
#pragma unroll
        for (int o = 16; o > 0; o >>= 1) p += __shfl_xor_sync(0xffffffffu, p, o);
        sc[k] = p * scale;
    }
    float m = sc[0];
#pragma unroll
    for (int k = 1; k < Kk; k++) m = fmaxf(m, sc[k]);
    float l = 0.f;
#pragma unroll
    for (int k = 0; k < Kk; k++) { sc[k] = expf(sc[k] - m); l += sc[k]; }
    float inv = 1.f / l;
    float o0 = 0.f, o1 = 0.f, o2 = 0.f, o3 = 0.f;
#pragma unroll
    for (int k = 0; k < Kk; k++) {
        float w = sc[k] * inv;
        const float* fr = fb + (size_t)idx[k] * Dd;
        o0 += w * fr[lane];
        o1 += w * fr[lane + 32];
        o2 += w * fr[lane + 64];
        o3 += w * fr[lane + 96];
    }
    float* hr = g_h + (size_t)(b * Nn + n) * Dd;
    hr[lane] = o0; hr[lane + 32] = o1; hr[lane + 64] = o2; hr[lane + 96] = o3;
}

// ---------------- tiled fp32 GEMM: C = A(MxK) * W(NxK)^T + bias ------------
__global__ void gemm_bias_kernel(const float* __restrict__ A, const float* __restrict__ W,
                                 const float* __restrict__ bias, float* __restrict__ C,
                                 int M, int Nd, int Kd, int relu) {
    const int BM = 64, BN = 64, BK = 16;
    __shared__ float As[BK][BM];
    __shared__ float Ws[BK][BN];
    int n0 = blockIdx.x * BN;
    int m0 = blockIdx.y * BM;
    int tid = threadIdx.x;
    int tx = tid & 15, ty = tid >> 4;
    int lr = tid >> 2;
    int lc = (tid & 3) * 4;
    float acc[4][4] = {};
    for (int k0 = 0; k0 < Kd; k0 += BK) {
        float4 av = *(const float4*)(A + (size_t)(m0 + lr) * Kd + k0 + lc);
        float4 wv = *(const float4*)(W + (size_t)(n0 + lr) * Kd + k0 + lc);
        As[lc + 0][lr] = av.x; As[lc + 1][lr] = av.y; As[lc + 2][lr] = av.z; As[lc + 3][lr] = av.w;
        Ws[lc + 0][lr] = wv.x; Ws[lc + 1][lr] = wv.y; Ws[lc + 2][lr] = wv.z; Ws[lc + 3][lr] = wv.w;
        __syncthreads();
#pragma unroll
        for (int k = 0; k < BK; k++) {
            float a[4], w[4];
#pragma unroll
            for (int i = 0; i < 4; i++) a[i] = As[k][ty * 4 + i];
#pragma unroll
            for (int j = 0; j < 4; j++) w[j] = Ws[k][tx * 4 + j];
#pragma unroll
            for (int i = 0; i < 4; i++)
#pragma unroll
                for (int j = 0; j < 4; j++) acc[i][j] += a[i] * w[j];
        }
        __syncthreads();
    }
#pragma unroll
    for (int i = 0; i < 4; i++) {
#pragma unroll
        for (int j = 0; j < 4; j++) {
            float v = acc[i][j] + bias[n0 + tx * 4 + j];
            if (relu) v = fmaxf(v, 0.f);
            C[(size_t)(m0 + ty * 4 + i) * Nd + n0 + tx * 4 + j] = v;
        }
    }
}

// ---------------- repack QKV (fp32, token-major) -> bf16 head-major --------
// q scaled by 1/sqrt(DH) * log2(e) so flash softmax can use exp2f.
__global__ void repack_qkv_kernel() {
    int i = blockIdx.x * 256 + threadIdx.x;
    if (i >= Bb * Nn * Dd) return;
    int d = i & 127;
    int n = (i >> 7) & (Nn - 1);
    int b = i >> 19;
    const float* base = g_qkv + (size_t)(b * Nn + n) * 384;
    int h = d >> 4, dd = d & 15;
    size_t bh = (size_t)b * Hh + h;
    float q = base[d] * (0.25f * 1.44269504f);
    float k = base[128 + d];
    float v = base[256 + d];
    g_qbf[(bh * Nn + n) * DHh + dd] = __float2bfloat16(q);
    g_kbf[(bh * Nn + n) * DHh + dd] = __float2bfloat16(k);
    g_vtbf[(bh * DHh + dd) * Nn + n] = __float2bfloat16(v);
}

// ---------------- flash attention: warp mma m16n8k16 bf16 ------------------
// block = 128 threads (4 warps), each warp owns 16 query rows; 64-key tiles.
__device__ __forceinline__ void mma16816(float* d, unsigned a0, unsigned a1,
                                         unsigned a2, unsigned a3,
                                         unsigned b0, unsigned b1) {
    asm volatile(
        "mma.sync.aligned.m16n8k16.row.col.f32.bf16.bf16.f32 "
        "{%0,%1,%2,%3}, {%4,%5,%6,%7}, {%8,%9}, {%0,%1,%2,%3};"
        : "+f"(d[0]), "+f"(d[1]), "+f"(d[2]), "+f"(d[3])
        : "r"(a0), "r"(a1), "r"(a2), "r"(a3), "r"(b0), "r"(b1));
}

__global__ void flash_mha_kernel() {
    int b = blockIdx.z, h = blockIdx.y;
    int tid = threadIdx.x;
    int warp = tid >> 5, lane = tid & 31;
    int q0 = blockIdx.x * 64 + warp * 16;
    size_t bh = (size_t)b * Hh + h;
    const __nv_bfloat16* qp = g_qbf + bh * Nn * DHh;
    const __nv_bfloat16* kp = g_kbf + bh * Nn * DHh;
    const __nv_bfloat16* vp = g_vtbf + bh * DHh * Nn;

    __shared__ __nv_bfloat16 Ks[64 * 16];   // [key][d]
    __shared__ __nv_bfloat16 Vts[16 * 64];  // [d][key]

    int r = lane >> 2;
    int c = lane & 3;

    // Q fragments (row-major A frags), loaded once
    unsigned qa0 = *(const unsigned*)(qp + (size_t)(q0 + r) * 16 + 2 * c);
    unsigned qa1 = *(const unsigned*)(qp + (size_t)(q0 + r + 8) * 16 + 2 * c);
    unsigned qa2 = *(const unsigned*)(qp + (size_t)(q0 + r) * 16 + 2 * c + 8);
    unsigned qa3 = *(const unsigned*)(qp + (size_t)(q0 + r + 8) * 16 + 2 * c + 8);

    float o[2][4] = {};
    float m0 = -1e30f, m1 = -1e30f, l0 = 0.f, l1 = 0.f;

    for (int kt = 0; kt < Nn; kt += 64) {
        // cooperative tile loads: 1024 halves each = 128 uint4
        *(uint4*)(Ks + tid * 8) = *(const uint4*)(kp + (size_t)kt * 16 + tid * 8);
        *(uint4*)(Vts + (tid >> 3) * 64 + (tid & 7) * 8) =
            *(const uint4*)(vp + (size_t)(tid >> 3) * Nn + kt + (tid & 7) * 8);
        __syncthreads();

        // S = Q K^T  (16 x 64), 8 n-tiles
        float s[8][4];
#pragma unroll
        for (int t = 0; t < 8; t++) {
            s[t][0] = s[t][1] = s[t][2] = s[t][3] = 0.f;
            unsigned b0 = *(const unsigned*)(Ks + (t * 8 + r) * 16 + 2 * c);
            unsigned b1 = *(const unsigned*)(Ks + (t * 8 + r) * 16 + 2 * c + 8);
            mma16816(s[t], qa0, qa1, qa2, qa3, b0, b1);
        }

        // online softmax (log2 domain; q pre-scaled by log2e/sqrt(DH))
        float mx0 = -1e30f, mx1 = -1e30f;
#pragma unroll
        for (int t = 0; t < 8; t++) {
            mx0 = fmaxf(mx0, fmaxf(s[t][0], s[t][1]));
            mx1 = fmaxf(mx1, fmaxf(s[t][2], s[t][3]));
        }
        mx0 = fmaxf(mx0, __shfl_xor_sync(0xffffffffu, mx0, 1));
        mx0 = fmaxf(mx0, __shfl_xor_sync(0xffffffffu, mx0, 2));
        mx1 = fmaxf(mx1, __shfl_xor_sync(0xffffffffu, mx1, 1));
        mx1 = fmaxf(mx1, __shfl_xor_sync(0xffffffffu, mx1, 2));
        float nm0 = fmaxf(m0, mx0);
        float nm1 = fmaxf(m1, mx1);
        float cor0 = exp2f(m0 - nm0);
        float cor1 = exp2f(m1 - nm1);
        m0 = nm0; m1 = nm1;

        unsigned p01[8], p23[8];
        float rs0 = 0.f, rs1 = 0.f;
#pragma unroll
        for (int t = 0; t < 8; t++) {
            float p0 = exp2f(s[t][0] - m0);
            float p1 = exp2f(s[t][1] - m0);
            float p2 = exp2f(s[t][2] - m1);
            float p3 = exp2f(s[t][3] - m1);
            rs0 += p0 + p1;
            rs1 += p2 + p3;
            __nv_bfloat162 x01 = __floats2bfloat162_rn(p0, p1);
            __nv_bfloat162 x23 = __floats2bfloat162_rn(p2, p3);
            p01[t] = *(unsigned*)&x01;
            p23[t] = *(unsigned*)&x23;
        }
        rs0 += __shfl_xor_sync(0xffffffffu, rs0, 1);
        rs0 += __shfl_xor_sync(0xffffffffu, rs0, 2);
        rs1 += __shfl_xor_sync(0xffffffffu, rs1, 1);
        rs1 += __shfl_xor_sync(0xffffffffu, rs1, 2);
        l0 = l0 * cor0 + rs0;
        l1 = l1 * cor1 + rs1;
#pragma unroll
        for (int d = 0; d < 2; d++) {
            o[d][0] *= cor0; o[d][1] *= cor0;
            o[d][2] *= cor1; o[d][3] *= cor1;
        }

        // O += P V  (k = 64 keys in 4 steps of 16)
#pragma unroll
        for (int st = 0; st < 4; st++) {
            unsigned a0 = p01[2 * st];
            unsigned a1 = p23[2 * st];
            unsigned a2 = p01[2 * st + 1];
            unsigned a3 = p23[2 * st + 1];
#pragma unroll
            for (int d = 0; d < 2; d++) {
                unsigned b0 = *(const unsigned*)(Vts + (d * 8 + r) * 64 + st * 16 + 2 * c);
                unsigned b1 = *(const unsigned*)(Vts + (d * 8 + r) * 64 + st * 16 + 2 * c + 8);
                mma16816(o[d], a0, a1, a2, a3, b0, b1);
            }
        }
        __syncthreads();
    }

    float inv0 = 1.f / l0;
    float inv1 = 1.f / l1;
    float* op = g_attn + ((size_t)b * Nn + q0) * Dd + h * 16;
#pragma unroll
    for (int d = 0; d < 2; d++) {
        float2 v0 = make_float2(o[d][0] * inv0, o[d][1] * inv0);
        float2 v1 = make_float2(o[d][2] * inv1, o[d][3] * inv1);
        *(float2*)(op + (size_t)r * Dd + d * 8 + 2 * c) = v0;
        *(float2*)(op + (size_t)(r + 8) * Dd + d * 8 + 2 * c) = v1;
    }
}

// ---------------- fused residual-add + LayerNorm (warp per row) ------------
__global__ void add_ln_kernel(float* __restrict__ h, const float* __restrict__ r,
                              const float* __restrict__ w, const float* __restrict__ bg) {
    int row = blockIdx.x * 8 + (threadIdx.x >> 5);
    int lane = threadIdx.x & 31;
    float* hp = h + (size_t)row * Dd;
    const float* rp = r + (size_t)row * Dd;
    float v[4];
    float s = 0.f;
#pragma unroll
    for (int i = 0; i < 4; i++) {
        v[i] = hp[lane + 32 * i] + rp[lane + 32 * i];
        s += v[i];
    }
#pragma unroll
    for (int o = 16; o > 0; o >>= 1) s += __shfl_xor_sync(0xffffffffu, s, o);
    float mean = s * (1.f / Dd);
    float var = 0.f;
#pragma unroll
    for (int i = 0; i < 4; i++) {
        float t = v[i] - mean;
        var += t * t;
    }
#pragma unroll
    for (int o = 16; o > 0; o >>= 1) var += __shfl_xor_sync(0xffffffffu, var, o);
    float inv = rsqrtf(var * (1.f / Dd) + 1e-5f);
#pragma unroll
    for (int i = 0; i < 4; i++)
        hp[lane + 32 * i] = (v[i] - mean) * inv * w[lane + 32 * i] + bg[lane + 32 * i];
}

// ---------------- mean pool over N ----------------------------------------
__global__ void pool_kernel() {
    int b = blockIdx.x;
    int d = threadIdx.x;
    float s = 0.f;
    for (int n = 0; n < Nn; n++) s += g_h[((size_t)b * Nn + n) * Dd + d];
    g_pooled[b * Dd + d] = s * (1.f / Nn);
}

// ---------------- final MLP head -------------------------------------------
__global__ void head_kernel(const float* __restrict__ fc1w, const float* __restrict__ fc1b,
                            const float* __restrict__ fc2w, const float* __restrict__ fc2b,
                            float* __restrict__ out) {
    int b = blockIdx.x;
    __shared__ float ps[128];
    float partial = 0.f;
    for (int f = threadIdx.x; f < FFf; f += 128) {
        float s = fc1b[f];
#pragma unroll 4
        for (int d = 0; d < Dd; d++) s += g_pooled[b * Dd + d] * fc1w[f * Dd + d];
        s = fmaxf(s, 0.f);
        partial += s * fc2w[f];
    }
    ps[threadIdx.x] = partial;
    __syncthreads();
    for (int s = 64; s > 0; s >>= 1) {
        if (threadIdx.x < s) ps[threadIdx.x] += ps[threadIdx.x + s];
        __syncthreads();
    }
    if (threadIdx.x == 0) {
        float z = ps[0] + fc2b[0];
        out[b] = 1.f / (1.f + expf(-z));
    }
}

// ---------------- host launcher --------------------------------------------
extern "C" void kernel_launch(void* const* d_in, const int* in_sizes, int n_in,
                              void* d_out, int out_size) {
    const float* x       = (const float*)d_in[0];
    const float* xyz_w   = (const float*)d_in[1];
    const float* xyz_b   = (const float*)d_in[2];
    const float* ohe_w   = (const float*)d_in[3];
    const float* ohe_b   = (const float*)d_in[4];
    const float* in_w    = (const float*)d_in[5];
    const float* in_b    = (const float*)d_in[6];
    const float* out_w   = (const float*)d_in[7];
    const float* out_b   = (const float*)d_in[8];
    const float* ln1_w   = (const float*)d_in[9];
    const float* ln1_b   = (const float*)d_in[10];
    const float* lin1_w  = (const float*)d_in[11];
    const float* lin1_b  = (const float*)d_in[12];
    const float* lin2_w  = (const float*)d_in[13];
    const float* lin2_b  = (const float*)d_in[14];
    const float* ln2_w   = (const float*)d_in[15];
    const float* ln2_b   = (const float*)d_in[16];
    const float* fc1_w   = (const float*)d_in[17];
    const float* fc1_b   = (const float*)d_in[18];
    const float* fc2_w   = (const float*)d_in[19];
    const float* fc2_b   = (const float*)d_in[20];
    float* out = (float*)d_out;

    float *p_h, *p_qkv, *p_attn, *p_ff;
    cudaGetSymbolAddress((void**)&p_h, g_h);
    cudaGetSymbolAddress((void**)&p_qkv, g_qkv);
    cudaGetSymbolAddress((void**)&p_attn, g_attn);
    cudaGetSymbolAddress((void**)&p_ff, g_ff);

    const int M = Bb * Nn;  // 32768

    embed_kernel<<<(Bb * Nn * Dd + 255) / 256, 256>>>(x, xyz_w, xyz_b, ohe_w, ohe_b);
    knn_select_kernel<<<dim3(Nn, Bb), 128>>>(x);
    knn_attn_kernel<<<(Bb * Nn * 32 + 127) / 128, 128>>>();

    for (int l = 0; l < Ll; l++) {
        gemm_bias_kernel<<<dim3(384 / 64, M / 64), 256>>>(
            p_h, in_w + (size_t)l * 384 * 128, in_b + (size_t)l * 384, p_qkv, M, 384, 128, 0);
        repack_qkv_kernel<<<(Bb * Nn * Dd + 255) / 256, 256>>>();
        flash_mha_kernel<<<dim3(Nn / 64, Hh, Bb), 128>>>();
        gemm_bias_kernel<<<dim3(128 / 64, M / 64), 256>>>(
            p_attn, out_w + (size_t)l * 128 * 128, out_b + (size_t)l * 128, p_qkv, M, 128, 128, 0);
        add_ln_kernel<<<M / 8, 256>>>(p_h, p_qkv, ln1_w + l * 128, ln1_b + l * 128);
        gemm_bias_kernel<<<dim3(512 / 64, M / 64), 256>>>(
            p_h, lin1_w + (size_t)l * 512 * 128, lin1_b + (size_t)l * 512, p_ff, M, 512, 128, 1);
        gemm_bias_kernel<<<dim3(128 / 64, M / 64), 256>>>(
            p_ff, lin2_w + (size_t)l * 128 * 512, lin2_b + (size_t)l * 128, p_qkv, M, 128, 512, 0);
        add_ln_kernel<<<M / 8, 256>>>(p_h, p_qkv, ln2_w + l * 128, ln2_b + l * 128);
    }

    pool_kernel<<<Bb, Dd>>>();
    head_kernel<<<Bb, 128>>>(fc1_w, fc1_b, fc2_w, fc2_b, out);
}

// round 4
// speedup vs baseline: 2.5106x; 1.2591x over previous
#include <cuda_runtime.h>
#include <cuda_bf16.h>
#include <math.h>
#include <stdint.h>

#define Bb 8
#define Nn 4096
#define Dd 128
#define Hh 8
#define DHh 16
#define FFf 512
#define Kk 16
#define Ll 2

// ---------------- scratch (static device globals; no allocations) ----------
__device__ float g_feat[Bb * Nn * Dd];        // 16 MB
__device__ float g_h[Bb * Nn * Dd];           // 16 MB (fp32 residual stream)
__device__ float g_tmp[Bb * Nn * Dd];         // 16 MB (fp32 GEMM outputs pre-LN)
__device__ int   g_knn[Bb * Nn * Kk];
__device__ float g_pooled[Bb * Dd];
// bf16 operands
__device__ __nv_bfloat16 g_hbf[Bb * Nn * Dd];        // bf16 shadow of h (GEMM A input)
__device__ __nv_bfloat16 g_attnbf[Bb * Nn * Dd];     // attention output (bf16)
__device__ __nv_bfloat16 g_ffbf[Bb * Nn * FFf];      // relu(ff1) bf16
__device__ __nv_bfloat16 g_qbf[Bb * Hh * Nn * DHh];  // head-major Q (pre-scaled)
__device__ __nv_bfloat16 g_kbf[Bb * Hh * Nn * DHh];  // head-major K
__device__ __nv_bfloat16 g_vtbf[Bb * Hh * DHh * Nn]; // V transposed [bh][d][n]

// ---------------- mma helper ------------------------------------------------
__device__ __forceinline__ void mma16816(float* d, unsigned a0, unsigned a1,
                                         unsigned a2, unsigned a3,
                                         unsigned b0, unsigned b1) {
    asm volatile(
        "mma.sync.aligned.m16n8k16.row.col.f32.bf16.bf16.f32 "
        "{%0,%1,%2,%3}, {%4,%5,%6,%7}, {%8,%9}, {%0,%1,%2,%3};"
        : "+f"(d[0]), "+f"(d[1]), "+f"(d[2]), "+f"(d[3])
        : "r"(a0), "r"(a1), "r"(a2), "r"(a3), "r"(b0), "r"(b1));
}

// ---------------- embed: feat = xyz@W1^T + b1 + ohe@W2^T + b2 --------------
__global__ void embed_kernel(const float* __restrict__ x,
                             const float* __restrict__ xyz_w, const float* __restrict__ xyz_b,
                             const float* __restrict__ ohe_w, const float* __restrict__ ohe_b) {
    int i = blockIdx.x * blockDim.x + threadIdx.x;
    if (i >= Bb * Nn * Dd) return;
    int d = i & (Dd - 1);
    int bn = i >> 7;
    const float* xr = x + (size_t)bn * 8;
    float acc = xyz_b[d] + ohe_b[d];
#pragma unroll
    for (int j = 0; j < 3; j++) acc += xr[j] * xyz_w[d * 3 + j];
#pragma unroll
    for (int j = 0; j < 5; j++) acc += xr[3 + j] * ohe_w[d * 5 + j];
    g_feat[i] = acc;
}

// ---------------- exact KNN: top K+1 smallest d2, drop self ----------------
__global__ void knn_select_kernel(const float* __restrict__ x) {
    int b = blockIdx.y, n = blockIdx.x;
    __shared__ float d2s[Nn];
    __shared__ float bv[128];
    __shared__ int bi[128];
    const float* xb = x + (size_t)b * Nn * 8;
    float qx = xb[n * 8 + 0], qy = xb[n * 8 + 1], qz = xb[n * 8 + 2];
    for (int j = threadIdx.x; j < Nn; j += 128) {
        float dx = xb[j * 8 + 0] - qx;
        float dy = xb[j * 8 + 1] - qy;
        float dz = xb[j * 8 + 2] - qz;
        d2s[j] = dx * dx + dy * dy + dz * dz;
    }
    __syncthreads();
    for (int it = 0; it <= Kk; ++it) {
        float mv = 3.4e38f;
        int mi = 0x7fffffff;
        for (int j = threadIdx.x; j < Nn; j += 128) {
            float v = d2s[j];
            if (v < mv) { mv = v; mi = j; }
        }
        bv[threadIdx.x] = mv;
        bi[threadIdx.x] = mi;
        __syncthreads();
        for (int s = 64; s > 0; s >>= 1) {
            if (threadIdx.x < s) {
                float v2 = bv[threadIdx.x + s];
                int i2 = bi[threadIdx.x + s];
                if (v2 < bv[threadIdx.x] ||
                    (v2 == bv[threadIdx.x] && i2 < bi[threadIdx.x])) {
                    bv[threadIdx.x] = v2;
                    bi[threadIdx.x] = i2;
                }
            }
            __syncthreads();
        }
        if (threadIdx.x == 0) {
            int sel = bi[0];
            d2s[sel] = 3.4e38f;
            if (it > 0) g_knn[((size_t)b * Nn + n) * Kk + (it - 1)] = sel;
        }
        __syncthreads();
    }
}

// ---------------- KNN attention: one warp per (b,n); writes h + hbf --------
__global__ void knn_attn_kernel() {
    int gw = (blockIdx.x * blockDim.x + threadIdx.x) >> 5;
    int lane = threadIdx.x & 31;
    if (gw >= Bb * Nn) return;
    int b = gw >> 12;
    int n = gw & (Nn - 1);
    const float* fb = g_feat + (size_t)b * Nn * Dd;
    const float* qr = fb + (size_t)n * Dd;
    float q0 = qr[lane], q1 = qr[lane + 32], q2 = qr[lane + 64], q3 = qr[lane + 96];
    const int* idxp = g_knn + (size_t)gw * Kk;
    int idx[Kk];
#pragma unroll
    for (int k = 0; k < Kk; k++) idx[k] = idxp[k];
    float sc[Kk];
    const float scale = 0.08838834764831845f;
#pragma unroll
    for (int k = 0; k < Kk; k++) {
        const float* fr = fb + (size_t)idx[k] * Dd;
        float p = q0 * fr[lane] + q1 * fr[lane + 32] + q2 * fr[lane + 64] + q3 * fr[lane + 96];
#pragma unroll
        for (int o = 16; o > 0; o >>= 1) p += __shfl_xor_sync(0xffffffffu, p, o);
        sc[k] = p * scale;
    }
    float m = sc[0];
#pragma unroll
    for (int k = 1; k < Kk; k++) m = fmaxf(m, sc[k]);
    float l = 0.f;
#pragma unroll
    for (int k = 0; k < Kk; k++) { sc[k] = expf(sc[k] - m); l += sc[k]; }
    float inv = 1.f / l;
    float o0 = 0.f, o1 = 0.f, o2 = 0.f, o3 = 0.f;
#pragma unroll
    for (int k = 0; k < Kk; k++) {
        float w = sc[k] * inv;
        const float* fr = fb + (size_t)idx[k] * Dd;
        o0 += w * fr[lane];
        o1 += w * fr[lane + 32];
        o2 += w * fr[lane + 64];
        o3 += w * fr[lane + 96];
    }
    size_t base = (size_t)(b * Nn + n) * Dd;
    g_h[base + lane] = o0; g_h[base + lane + 32] = o1;
    g_h[base + lane + 64] = o2; g_h[base + lane + 96] = o3;
    g_hbf[base + lane] = __float2bfloat16(o0);
    g_hbf[base + lane + 32] = __float2bfloat16(o1);
    g_hbf[base + lane + 64] = __float2bfloat16(o2);
    g_hbf[base + lane + 96] = __float2bfloat16(o3);
}

// ---------------- bf16 tensor-core GEMM: C = A(MxK,bf16) * W(NxK,f32)^T + b -
// block: 256 thr (8 warps), tile 128(M) x 64(N), K staged 64 at a time.
// mode 0: fp32 out. mode 1: relu + bf16 out. mode 2: QKV scatter.
#define GMODE_F32  0
#define GMODE_RELU 1
#define GMODE_QKV  2

__device__ __forceinline__ void qkv_store(int m, int n, float v0, float v1) {
    int b = m >> 12, tok = m & (Nn - 1);
    if (n < 128) {  // Q, fold softmax scale + log2e
        int hh = n >> 4, dd = n & 15;
        const float s = 0.25f * 1.44269504f;
        __nv_bfloat162 q = __floats2bfloat162_rn(v0 * s, v1 * s);
        *(__nv_bfloat162*)&g_qbf[(((size_t)(b * Hh + hh) * Nn) + tok) * DHh + dd] = q;
    } else if (n < 256) {  // K
        int d = n - 128, hh = d >> 4, dd = d & 15;
        __nv_bfloat162 k2 = __floats2bfloat162_rn(v0, v1);
        *(__nv_bfloat162*)&g_kbf[(((size_t)(b * Hh + hh) * Nn) + tok) * DHh + dd] = k2;
    } else {  // V -> transposed
        int d = n - 256, hh = d >> 4, dd = d & 15;
        size_t base = ((size_t)(b * Hh + hh) * DHh + dd) * Nn + tok;
        g_vtbf[base] = __float2bfloat16(v0);
        g_vtbf[base + Nn] = __float2bfloat16(v1);
    }
}

__global__ void gemm_bf16_kernel(const __nv_bfloat16* __restrict__ A,
                                 const float* __restrict__ W,
                                 const float* __restrict__ bias,
                                 float* __restrict__ Cf,
                                 __nv_bfloat16* __restrict__ Cbf,
                                 int M, int Nd, int Kd, int mode) {
    __shared__ __nv_bfloat16 As[128][72];
    __shared__ __nv_bfloat16 Ws[64][72];
    int tid = threadIdx.x, warp = tid >> 5, lane = tid & 31;
    int m0 = blockIdx.y * 128, n0 = blockIdx.x * 64;
    int mw = (warp & 3) * 32, nw = (warp >> 2) * 32;
    int r = lane >> 2, c = lane & 3;
    float acc[2][4][4] = {};

    for (int k0 = 0; k0 < Kd; k0 += 64) {
        // load A tile 128x64 bf16
        {
            int row = tid >> 1;
            int colb = (tid & 1) * 32;
            const __nv_bfloat16* ap = A + (size_t)(m0 + row) * Kd + k0 + colb;
#pragma unroll
            for (int i = 0; i < 4; i++)
                *(uint4*)&As[row][colb + i * 8] = *(const uint4*)(ap + i * 8);
        }
        // load W tile 64x64 fp32 -> bf16
        {
            int row = tid >> 2;
            int colb = (tid & 3) * 16;
            const float* wp = W + (size_t)(n0 + row) * Kd + k0 + colb;
#pragma unroll
            for (int j = 0; j < 4; j++) {
                float4 f = *(const float4*)(wp + j * 4);
                __nv_bfloat162 lo = __floats2bfloat162_rn(f.x, f.y);
                __nv_bfloat162 hi = __floats2bfloat162_rn(f.z, f.w);
                *(__nv_bfloat162*)&Ws[row][colb + j * 4] = lo;
                *(__nv_bfloat162*)&Ws[row][colb + j * 4 + 2] = hi;
            }
        }
        __syncthreads();
#pragma unroll
        for (int ks = 0; ks < 4; ks++) {
            int kk = ks * 16;
            unsigned a[2][4], bf[4][2];
#pragma unroll
            for (int mi = 0; mi < 2; mi++) {
                a[mi][0] = *(unsigned*)&As[mw + mi * 16 + r][kk + 2 * c];
                a[mi][1] = *(unsigned*)&As[mw + mi * 16 + r + 8][kk + 2 * c];
                a[mi][2] = *(unsigned*)&As[mw + mi * 16 + r][kk + 2 * c + 8];
                a[mi][3] = *(unsigned*)&As[mw + mi * 16 + r + 8][kk + 2 * c + 8];
            }
#pragma unroll
            for (int ni = 0; ni < 4; ni++) {
                bf[ni][0] = *(unsigned*)&Ws[nw + ni * 8 + r][kk + 2 * c];
                bf[ni][1] = *(unsigned*)&Ws[nw + ni * 8 + r][kk + 2 * c + 8];
            }
#pragma unroll
            for (int mi = 0; mi < 2; mi++)
#pragma unroll
                for (int ni = 0; ni < 4; ni++)
                    mma16816(acc[mi][ni], a[mi][0], a[mi][1], a[mi][2], a[mi][3],
                             bf[ni][0], bf[ni][1]);
        }
        __syncthreads();
    }

    // epilogue
#pragma unroll
    for (int mi = 0; mi < 2; mi++) {
#pragma unroll
        for (int ni = 0; ni < 4; ni++) {
            int n = n0 + nw + ni * 8 + 2 * c;
            float b0 = bias[n], b1 = bias[n + 1];
            int mA = m0 + mw + mi * 16 + r;
            int mB = mA + 8;
            float v0 = acc[mi][ni][0] + b0, v1 = acc[mi][ni][1] + b1;
            float v2 = acc[mi][ni][2] + b0, v3 = acc[mi][ni][3] + b1;
            if (mode == GMODE_F32) {
                *(float2*)&Cf[(size_t)mA * Nd + n] = make_float2(v0, v1);
                *(float2*)&Cf[(size_t)mB * Nd + n] = make_float2(v2, v3);
            } else if (mode == GMODE_RELU) {
                __nv_bfloat162 x0 = __floats2bfloat162_rn(fmaxf(v0, 0.f), fmaxf(v1, 0.f));
                __nv_bfloat162 x1 = __floats2bfloat162_rn(fmaxf(v2, 0.f), fmaxf(v3, 0.f));
                *(__nv_bfloat162*)&Cbf[(size_t)mA * Nd + n] = x0;
                *(__nv_bfloat162*)&Cbf[(size_t)mB * Nd + n] = x1;
            } else {
                qkv_store(mA, n, v0, v1);
                qkv_store(mB, n, v2, v3);
            }
        }
    }
}

// ---------------- flash attention: warp mma m16n8k16 bf16 ------------------
__global__ void flash_mha_kernel() {
    int b = blockIdx.z, h = blockIdx.y;
    int tid = threadIdx.x;
    int warp = tid >> 5, lane = tid & 31;
    int q0 = blockIdx.x * 64 + warp * 16;
    size_t bh = (size_t)b * Hh + h;
    const __nv_bfloat16* qp = g_qbf + bh * Nn * DHh;
    const __nv_bfloat16* kp = g_kbf + bh * Nn * DHh;
    const __nv_bfloat16* vp = g_vtbf + bh * DHh * Nn;

    __shared__ __nv_bfloat16 Ks[64 * 16];   // [key][d]
    __shared__ __nv_bfloat16 Vts[16 * 64];  // [d][key]

    int r = lane >> 2;
    int c = lane & 3;

    unsigned qa0 = *(const unsigned*)(qp + (size_t)(q0 + r) * 16 + 2 * c);
    unsigned qa1 = *(const unsigned*)(qp + (size_t)(q0 + r + 8) * 16 + 2 * c);
    unsigned qa2 = *(const unsigned*)(qp + (size_t)(q0 + r) * 16 + 2 * c + 8);
    unsigned qa3 = *(const unsigned*)(qp + (size_t)(q0 + r + 8) * 16 + 2 * c + 8);

    float o[2][4] = {};
    float m0 = -1e30f, m1 = -1e30f, l0 = 0.f, l1 = 0.f;

    for (int kt = 0; kt < Nn; kt += 64) {
        *(uint4*)(Ks + tid * 8) = *(const uint4*)(kp + (size_t)kt * 16 + tid * 8);
        *(uint4*)(Vts + (tid >> 3) * 64 + (tid & 7) * 8) =
            *(const uint4*)(vp + (size_t)(tid >> 3) * Nn + kt + (tid & 7) * 8);
        __syncthreads();

        float s[8][4];
#pragma unroll
        for (int t = 0; t < 8; t++) {
            s[t][0] = s[t][1] = s[t][2] = s[t][3] = 0.f;
            unsigned b0 = *(const unsigned*)(Ks + (t * 8 + r) * 16 + 2 * c);
            unsigned b1 = *(const unsigned*)(Ks + (t * 8 + r) * 16 + 2 * c + 8);
            mma16816(s[t], qa0, qa1, qa2, qa3, b0, b1);
        }

        float mx0 = -1e30f, mx1 = -1e30f;
#pragma unroll
        for (int t = 0; t < 8; t++) {
            mx0 = fmaxf(mx0, fmaxf(s[t][0], s[t][1]));
            mx1 = fmaxf(mx1, fmaxf(s[t][2], s[t][3]));
        }
        mx0 = fmaxf(mx0, __shfl_xor_sync(0xffffffffu, mx0, 1));
        mx0 = fmaxf(mx0, __shfl_xor_sync(0xffffffffu, mx0, 2));
        mx1 = fmaxf(mx1, __shfl_xor_sync(0xffffffffu, mx1, 1));
        mx1 = fmaxf(mx1, __shfl_xor_sync(0xffffffffu, mx1, 2));
        float nm0 = fmaxf(m0, mx0);
        float nm1 = fmaxf(m1, mx1);
        float cor0 = exp2f(m0 - nm0);
        float cor1 = exp2f(m1 - nm1);
        m0 = nm0; m1 = nm1;

        unsigned p01[8], p23[8];
        float rs0 = 0.f, rs1 = 0.f;
#pragma unroll
        for (int t = 0; t < 8; t++) {
            float p0 = exp2f(s[t][0] - m0);
            float p1 = exp2f(s[t][1] - m0);
            float p2 = exp2f(s[t][2] - m1);
            float p3 = exp2f(s[t][3] - m1);
            rs0 += p0 + p1;
            rs1 += p2 + p3;
            __nv_bfloat162 x01 = __floats2bfloat162_rn(p0, p1);
            __nv_bfloat162 x23 = __floats2bfloat162_rn(p2, p3);
            p01[t] = *(unsigned*)&x01;
            p23[t] = *(unsigned*)&x23;
        }
        rs0 += __shfl_xor_sync(0xffffffffu, rs0, 1);
        rs0 += __shfl_xor_sync(0xffffffffu, rs0, 2);
        rs1 += __shfl_xor_sync(0xffffffffu, rs1, 1);
        rs1 += __shfl_xor_sync(0xffffffffu, rs1, 2);
        l0 = l0 * cor0 + rs0;
        l1 = l1 * cor1 + rs1;
#pragma unroll
        for (int d = 0; d < 2; d++) {
            o[d][0] *= cor0; o[d][1] *= cor0;
            o[d][2] *= cor1; o[d][3] *= cor1;
        }

#pragma unroll
        for (int st = 0; st < 4; st++) {
            unsigned a0 = p01[2 * st];
            unsigned a1 = p23[2 * st];
            unsigned a2 = p01[2 * st + 1];
            unsigned a3 = p23[2 * st + 1];
#pragma unroll
            for (int d = 0; d < 2; d++) {
                unsigned b0 = *(const unsigned*)(Vts + (d * 8 + r) * 64 + st * 16 + 2 * c);
                unsigned b1 = *(const unsigned*)(Vts + (d * 8 + r) * 64 + st * 16 + 2 * c + 8);
                mma16816(o[d], a0, a1, a2, a3, b0, b1);
            }
        }
        __syncthreads();
    }

    float inv0 = 1.f / l0;
    float inv1 = 1.f / l1;
    __nv_bfloat16* op = g_attnbf + ((size_t)b * Nn + q0) * Dd + h * 16;
#pragma unroll
    for (int d = 0; d < 2; d++) {
        __nv_bfloat162 v0 = __floats2bfloat162_rn(o[d][0] * inv0, o[d][1] * inv0);
        __nv_bfloat162 v1 = __floats2bfloat162_rn(o[d][2] * inv1, o[d][3] * inv1);
        *(__nv_bfloat162*)(op + (size_t)r * Dd + d * 8 + 2 * c) = v0;
        *(__nv_bfloat162*)(op + (size_t)(r + 8) * Dd + d * 8 + 2 * c) = v1;
    }
}

// ---------------- fused residual-add + LayerNorm; writes h(f32) + hbf ------
__global__ void add_ln_kernel(float* __restrict__ h, const float* __restrict__ rsd,
                              const float* __restrict__ w, const float* __restrict__ bg) {
    int row = blockIdx.x * 8 + (threadIdx.x >> 5);
    int lane = threadIdx.x & 31;
    float* hp = h + (size_t)row * Dd;
    const float* rp = rsd + (size_t)row * Dd;
    float v[4];
    float s = 0.f;
#pragma unroll
    for (int i = 0; i < 4; i++) {
        v[i] = hp[lane + 32 * i] + rp[lane + 32 * i];
        s += v[i];
    }
#pragma unroll
    for (int o = 16; o > 0; o >>= 1) s += __shfl_xor_sync(0xffffffffu, s, o);
    float mean = s * (1.f / Dd);
    float var = 0.f;
#pragma unroll
    for (int i = 0; i < 4; i++) {
        float t = v[i] - mean;
        var += t * t;
    }
#pragma unroll
    for (int o = 16; o > 0; o >>= 1) var += __shfl_xor_sync(0xffffffffu, var, o);
    float inv = rsqrtf(var * (1.f / Dd) + 1e-5f);
#pragma unroll
    for (int i = 0; i < 4; i++) {
        float y = (v[i] - mean) * inv * w[lane + 32 * i] + bg[lane + 32 * i];
        hp[lane + 32 * i] = y;
        g_hbf[(size_t)row * Dd + lane + 32 * i] = __float2bfloat16(y);
    }
}

// ---------------- mean pool over N ----------------------------------------
__global__ void pool_kernel() {
    int b = blockIdx.x;
    int d = threadIdx.x;
    float s = 0.f;
    for (int n = 0; n < Nn; n++) s += g_h[((size_t)b * Nn + n) * Dd + d];
    g_pooled[b * Dd + d] = s * (1.f / Nn);
}

// ---------------- final MLP head -------------------------------------------
__global__ void head_kernel(const float* __restrict__ fc1w, const float* __restrict__ fc1b,
                            const float* __restrict__ fc2w, const float* __restrict__ fc2b,
                            float* __restrict__ out) {
    int b = blockIdx.x;
    __shared__ float ps[128];
    float partial = 0.f;
    for (int f = threadIdx.x; f < FFf; f += 128) {
        float s = fc1b[f];
#pragma unroll 4
        for (int d = 0; d < Dd; d++) s += g_pooled[b * Dd + d] * fc1w[f * Dd + d];
        s = fmaxf(s, 0.f);
        partial += s * fc2w[f];
    }
    ps[threadIdx.x] = partial;
    __syncthreads();
    for (int s = 64; s > 0; s >>= 1) {
        if (threadIdx.x < s) ps[threadIdx.x] += ps[threadIdx.x + s];
        __syncthreads();
    }
    if (threadIdx.x == 0) {
        float z = ps[0] + fc2b[0];
        out[b] = 1.f / (1.f + expf(-z));
    }
}

// ---------------- host launcher --------------------------------------------
extern "C" void kernel_launch(void* const* d_in, const int* in_sizes, int n_in,
                              void* d_out, int out_size) {
    const float* x       = (const float*)d_in[0];
    const float* xyz_w   = (const float*)d_in[1];
    const float* xyz_b   = (const float*)d_in[2];
    const float* ohe_w   = (const float*)d_in[3];
    const float* ohe_b   = (const float*)d_in[4];
    const float* in_w    = (const float*)d_in[5];
    const float* in_b    = (const float*)d_in[6];
    const float* out_w   = (const float*)d_in[7];
    const float* out_b   = (const float*)d_in[8];
    const float* ln1_w   = (const float*)d_in[9];
    const float* ln1_b   = (const float*)d_in[10];
    const float* lin1_w  = (const float*)d_in[11];
    const float* lin1_b  = (const float*)d_in[12];
    const float* lin2_w  = (const float*)d_in[13];
    const float* lin2_b  = (const float*)d_in[14];
    const float* ln2_w   = (const float*)d_in[15];
    const float* ln2_b   = (const float*)d_in[16];
    const float* fc1_w   = (const float*)d_in[17];
    const float* fc1_b   = (const float*)d_in[18];
    const float* fc2_w   = (const float*)d_in[19];
    const float* fc2_b   = (const float*)d_in[20];
    float* out = (float*)d_out;

    float *p_h, *p_tmp;
    __nv_bfloat16 *p_hbf, *p_attnbf, *p_ffbf;
    cudaGetSymbolAddress((void**)&p_h, g_h);
    cudaGetSymbolAddress((void**)&p_tmp, g_tmp);
    cudaGetSymbolAddress((void**)&p_hbf, g_hbf);
    cudaGetSymbolAddress((void**)&p_attnbf, g_attnbf);
    cudaGetSymbolAddress((void**)&p_ffbf, g_ffbf);

    const int M = Bb * Nn;  // 32768

    embed_kernel<<<(Bb * Nn * Dd + 255) / 256, 256>>>(x, xyz_w, xyz_b, ohe_w, ohe_b);
    knn_select_kernel<<<dim3(Nn, Bb), 128>>>(x);
    knn_attn_kernel<<<(Bb * Nn * 32 + 127) / 128, 128>>>();

    for (int l = 0; l < Ll; l++) {
        // qkv = hbf @ in_w^T + in_b  -> scatter to q/k/vt bf16 buffers
        gemm_bf16_kernel<<<dim3(384 / 64, M / 128), 256>>>(
            p_hbf, in_w + (size_t)l * 384 * 128, in_b + (size_t)l * 384,
            nullptr, nullptr, M, 384, 128, GMODE_QKV);
        flash_mha_kernel<<<dim3(Nn / 64, Hh, Bb), 128>>>();
        // out proj -> tmp fp32
        gemm_bf16_kernel<<<dim3(128 / 64, M / 128), 256>>>(
            p_attnbf, out_w + (size_t)l * 128 * 128, out_b + (size_t)l * 128,
            p_tmp, nullptr, M, 128, 128, GMODE_F32);
        add_ln_kernel<<<M / 8, 256>>>(p_h, p_tmp, ln1_w + l * 128, ln1_b + l * 128);
        // ff1 = relu(hbf @ lin1^T + b) -> bf16
        gemm_bf16_kernel<<<dim3(512 / 64, M / 128), 256>>>(
            p_hbf, lin1_w + (size_t)l * 512 * 128, lin1_b + (size_t)l * 512,
            nullptr, p_ffbf, M, 512, 128, GMODE_RELU);
        // f2 = ffbf @ lin2^T + b -> tmp fp32
        gemm_bf16_kernel<<<dim3(128 / 64, M / 128), 256>>>(
            p_ffbf, lin2_w + (size_t)l * 128 * 512, lin2_b + (size_t)l * 128,
            p_tmp, nullptr, M, 128, 512, GMODE_F32);
        add_ln_kernel<<<M / 8, 256>>>(p_h, p_tmp, ln2_w + l * 128, ln2_b + l * 128);
    }

    pool_kernel<<<Bb, Dd>>>();
    head_kernel<<<Bb, 128>>>(fc1_w, fc1_b, fc2_w, fc2_b, out);
}